// round 8
// baseline (speedup 1.0000x reference)
#include <cuda_runtime.h>
#include <cuda_bf16.h>
#include <math.h>
#include <stdint.h>

#define Bsz   128
#define Wd    128
#define FIN   64
#define NN    64
#define EE    4096
#define EDd   16
#define HC    128
#define FLATd 8192
#define HIDd  2048
#define SPLITK 16
#define GCHUNK 32

// ---------------- scratch ----------------
__device__ __align__(128) float g_xg[Bsz * NN * Wd];
__device__ __align__(128) float g_h[Bsz * NN * HC];
__device__ __align__(128) float g_xflat[Bsz * FLATd];
__device__ __align__(128) float g_h1part[SPLITK * Bsz * HIDd];
__device__ __align__(128) float g_h1[Bsz * HIDd];
__device__ int  g_csr_off[NN + 1];
__device__ int2 g_csr_es[EE];

// ---------------- helpers ----------------
__device__ __forceinline__ uint32_t smem_u32(const void* p) {
    uint32_t a;
    asm("{ .reg .u64 t; cvta.to.shared.u64 t, %1; cvt.u32.u64 %0, t; }" : "=r"(a) : "l"(p));
    return a;
}
__device__ __forceinline__ void ldm_x4(uint32_t (&r)[4], uint32_t addr) {
    asm volatile("ldmatrix.sync.aligned.m8n8.x4.shared.b16 {%0,%1,%2,%3}, [%4];"
        : "=r"(r[0]), "=r"(r[1]), "=r"(r[2]), "=r"(r[3]) : "r"(addr));
}
__device__ __forceinline__ void mma_bf16(float (&d)[4], const uint32_t (&a)[4],
                                         uint32_t b0, uint32_t b1) {
    asm volatile(
        "mma.sync.aligned.m16n8k16.row.col.f32.bf16.bf16.f32 "
        "{%0,%1,%2,%3}, {%4,%5,%6,%7}, {%8,%9}, {%0,%1,%2,%3};"
        : "+f"(d[0]), "+f"(d[1]), "+f"(d[2]), "+f"(d[3])
        : "r"(a[0]), "r"(a[1]), "r"(a[2]), "r"(a[3]), "r"(b0), "r"(b1));
}
__device__ __forceinline__ void cvtpair(float a, float b, uint32_t& hi, uint32_t& lo) {
    __nv_bfloat16 ha = __float2bfloat16(a), hb2 = __float2bfloat16(b);
    float ra = a - __bfloat162float(ha), rb = b - __bfloat162float(hb2);
    __nv_bfloat16 la = __float2bfloat16(ra), lb = __float2bfloat16(rb);
    hi = (uint32_t)__bfloat16_as_ushort(ha) | ((uint32_t)__bfloat16_as_ushort(hb2) << 16);
    lo = (uint32_t)__bfloat16_as_ushort(la) | ((uint32_t)__bfloat16_as_ushort(lb) << 16);
}
__device__ __forceinline__ void sts_v2(uint32_t addr, uint32_t x, uint32_t y) {
    asm volatile("st.shared.v2.b32 [%0], {%1,%2};" :: "r"(addr), "r"(x), "r"(y) : "memory");
}

// ---------------- CSR build ----------------
__global__ void k_csr(const int* __restrict__ ei) {
    __shared__ int cnt[NN];
    __shared__ int off[NN + 1];
    __shared__ int cur[NN];
    int tid = threadIdx.x;
    if (tid < NN) cnt[tid] = 0;
    __syncthreads();
    for (int e = tid; e < EE; e += blockDim.x)
        atomicAdd(&cnt[ei[EE + e]], 1);
    __syncthreads();
    if (tid == 0) {
        int run = 0;
        for (int k = 0; k < NN; k++) { off[k] = run; cur[k] = run; run += cnt[k]; }
        off[NN] = run;
    }
    __syncthreads();
    for (int e = tid; e < EE; e += blockDim.x) {
        int d = ei[EE + e];
        int pos = atomicAdd(&cur[d], 1);
        g_csr_es[pos] = make_int2(e, ei[e]);
    }
    if (tid <= NN) g_csr_off[tid] = off[tid];
}

// ---------------- TCN conv1d(k=3,pad=1) ----------------
__global__ void k_tcn(const float* __restrict__ x,
                      const float* __restrict__ tw,
                      const float* __restrict__ tb) {
    __shared__ float xs[FIN * 129];
    __shared__ float sw[16 * 192];
    int b = blockIdx.y, nc = blockIdx.x;
    int tid = threadIdx.x;
    const float* xb = x + (size_t)b * Wd * FIN;
    for (int idx = tid; idx < Wd * FIN; idx += 128) {
        int w = idx >> 6, i = idx & 63;
        xs[i * 129 + w] = xb[idx];
    }
    for (int idx = tid; idx < 16 * 192; idx += 128)
        sw[idx] = tw[nc * 16 * 192 + idx];
    __syncthreads();
    int w = tid;
    float acc[16];
#pragma unroll
    for (int nl = 0; nl < 16; nl++) acc[nl] = tb[nc * 16 + nl];
    for (int i = 0; i < FIN; i++) {
        float x0 = xs[i * 129 + w];
        float xm = (w > 0)   ? xs[i * 129 + w - 1] : 0.f;
        float xp = (w < 127) ? xs[i * 129 + w + 1] : 0.f;
#pragma unroll
        for (int nl = 0; nl < 16; nl++) {
            const float* wp = &sw[nl * 192 + i * 3];
            acc[nl] += xm * wp[0] + x0 * wp[1] + xp * wp[2];
        }
    }
#pragma unroll
    for (int nl = 0; nl < 16; nl++)
        g_xg[((size_t)b * NN + nc * 16 + nl) * Wd + w] = acc[nl];
}

// ---------------- lin_l projection ----------------
__global__ void k_linl(const float* __restrict__ lw, const float* __restrict__ lb) {
    __shared__ float xs[NN * 129];
    __shared__ float ws[64 * 33];
    int b = blockIdx.y, oc = blockIdx.x;
    int tid = threadIdx.x;
    for (int idx = tid; idx < NN * Wd; idx += 256) {
        int n = idx >> 7, w = idx & 127;
        xs[n * 129 + w] = g_xg[(size_t)b * NN * Wd + idx];
    }
    int tx = tid & 15, ty = tid >> 4;
    float acc[4][4];
#pragma unroll
    for (int i = 0; i < 4; i++)
#pragma unroll
        for (int j = 0; j < 4; j++) acc[i][j] = 0.f;
    for (int wc = 0; wc < 4; wc++) {
        __syncthreads();
        for (int idx = tid; idx < 64 * 32; idx += 256) {
            int ol = idx >> 5, wl = idx & 31;
            ws[ol * 33 + wl] = lw[(oc * 64 + ol) * Wd + wc * 32 + wl];
        }
        __syncthreads();
#pragma unroll 4
        for (int wl = 0; wl < 32; wl++) {
            float a[4], bb[4];
#pragma unroll
            for (int j = 0; j < 4; j++) a[j]  = xs[(ty * 4 + j) * 129 + wc * 32 + wl];
#pragma unroll
            for (int j = 0; j < 4; j++) bb[j] = ws[(tx * 4 + j) * 33 + wl];
#pragma unroll
            for (int i = 0; i < 4; i++)
#pragma unroll
                for (int j = 0; j < 4; j++) acc[i][j] += a[i] * bb[j];
        }
    }
#pragma unroll
    for (int i = 0; i < 4; i++)
#pragma unroll
        for (int j = 0; j < 4; j++) {
            int n = ty * 4 + i, o = oc * 64 + tx * 4 + j;
            g_h[((size_t)b * NN + n) * HC + o] = acc[i][j] + lb[o];
        }
}

// ---------------- GAT: tensor-core edge projection + chunked softmax ----------------
// Per 32-edge chunk: ea converted to bf16 hi/lo fragment layout during staging,
// each warp mma's its own 32 channels (3-term bf16 split, exact to ~2^-17),
// consumes ev from warp-private smem, transposed score reduce, online softmax.
__global__ void __launch_bounds__(128) k_gat(const float* __restrict__ eattr,
                      const float* __restrict__ lew,
                      const float* __restrict__ leb,
                      const float* __restrict__ att) {
    __shared__ int2     es_s[GCHUNK];              // (eid, src)
    __shared__ uint32_t bfrag[2][4][2][32];        // [hi/lo][ntile][reg][lane]
    __shared__ float    ev_s[GCHUNK * 132];        // [edge][ch(128)+pad]
    __shared__ float    p_s[4][32 * 33];           // per-warp transposed scores

    int n = blockIdx.x, b = blockIdx.y;
    int t = threadIdx.x, lane = t & 31, wd = t >> 5;
    int g = lane >> 2, tq = lane & 3;

    // --- A fragments: this warp's 32 channels of lin_e_w, bf16 hi/lo (once per block) ---
    uint32_t Ah[2][4], Al[2][4];
#pragma unroll
    for (int mt = 0; mt < 2; mt++) {
        int ch0 = wd * 32 + mt * 16 + g;
        const float* wr0 = lew + ch0 * EDd;
        const float* wr1 = lew + (ch0 + 8) * EDd;
        float2 p0 = *(const float2*)(wr0 + 2 * tq);
        float2 p1 = *(const float2*)(wr1 + 2 * tq);
        float2 p2 = *(const float2*)(wr0 + 2 * tq + 8);
        float2 p3 = *(const float2*)(wr1 + 2 * tq + 8);
        cvtpair(p0.x, p0.y, Ah[mt][0], Al[mt][0]);
        cvtpair(p1.x, p1.y, Ah[mt][1], Al[mt][1]);
        cvtpair(p2.x, p2.y, Ah[mt][2], Al[mt][2]);
        cvtpair(p3.x, p3.y, Ah[mt][3], Al[mt][3]);
    }

    float att_t = att[t];
    const float* hb = g_h + (size_t)b * NN * HC;
    float hdp = leb[t] + hb[n * HC + t];

    int beg = g_csr_off[n], end = g_csr_off[n + 1];
    int deg = end - beg;
    const int2* lst = g_csr_es + beg;
    const float* eab = eattr + (size_t)b * EE * EDd;

    float* prow = p_s[wd];
    float m = -1e30f, den = 0.f, acc = 0.f;

    for (int base = 0; base < deg; base += GCHUNK) {
        int cnt = min(GCHUNK, deg - base);
        if (t < GCHUNK) es_s[t] = (t < cnt) ? lst[base + t] : make_int2(0, 0);
        __syncthreads();

        // --- stage ea -> bf16 hi/lo B-fragments (128 tasks = 32 edges x 4 quads) ---
        {
            int j = t >> 2, q = t & 3;
            float4 ea4 = *(const float4*)(eab + (size_t)es_s[j].x * EDd + q * 4);
            uint32_t h0, l0, h1, l1;
            cvtpair(ea4.x, ea4.y, h0, l0);
            cvtpair(ea4.z, ea4.w, h1, l1);
            int nt = j >> 3, reg = q >> 1;
            int lpos = (j & 7) * 4 + (q & 1) * 2;
            bfrag[0][nt][reg][lpos] = h0; bfrag[0][nt][reg][lpos + 1] = h1;
            bfrag[1][nt][reg][lpos] = l0; bfrag[1][nt][reg][lpos + 1] = l1;
        }
        __syncthreads();

        // --- mma: ev[ch, e] for this warp's channels (3-term bf16 split) ---
#pragma unroll
        for (int nt = 0; nt < 4; nt++) {
            uint32_t b0h = bfrag[0][nt][0][lane], b1h = bfrag[0][nt][1][lane];
            uint32_t b0l = bfrag[1][nt][0][lane], b1l = bfrag[1][nt][1][lane];
#pragma unroll
            for (int mt = 0; mt < 2; mt++) {
                float a4[4] = {0.f, 0.f, 0.f, 0.f};
                mma_bf16(a4, Ah[mt], b0h, b1h);
                mma_bf16(a4, Ah[mt], b0l, b1l);
                mma_bf16(a4, Al[mt], b0h, b1h);
                int ch = wd * 32 + mt * 16 + g;
                int e0 = nt * 8 + 2 * tq;
                ev_s[e0 * 132 + ch]           = a4[0];
                ev_s[(e0 + 1) * 132 + ch]     = a4[1];
                ev_s[e0 * 132 + ch + 8]       = a4[2];
                ev_s[(e0 + 1) * 132 + ch + 8] = a4[3];
            }
        }
        __syncwarp();

        // --- pass 1: scores into transposed smem ---
        for (int jj = 0; jj < cnt; jj++) {
            float hs = hb[es_s[jj].y * HC + t];
            float z = hdp + hs + ev_s[jj * 132 + t];
            prow[jj * 33 + lane] = fmaxf(z, 0.01f * z) * att_t;
        }
        __syncwarp();
        float sq = -1e30f;
        if (lane < cnt) {
            const float* rp = &prow[lane * 33];
            float s0 = 0.f, s1 = 0.f, s2 = 0.f, s3 = 0.f;
#pragma unroll
            for (int c4 = 0; c4 < 8; c4++) {
                s0 += rp[c4 * 4 + 0];
                s1 += rp[c4 * 4 + 1];
                s2 += rp[c4 * 4 + 2];
                s3 += rp[c4 * 4 + 3];
            }
            sq = (s0 + s1) + (s2 + s3);
        }
        __syncwarp();

        // --- pass 2: chunk max / weight / denom ---
        float cm = sq;
        cm = fmaxf(cm, __shfl_xor_sync(0xffffffffu, cm, 16));
        cm = fmaxf(cm, __shfl_xor_sync(0xffffffffu, cm, 8));
        cm = fmaxf(cm, __shfl_xor_sync(0xffffffffu, cm, 4));
        cm = fmaxf(cm, __shfl_xor_sync(0xffffffffu, cm, 2));
        cm = fmaxf(cm, __shfl_xor_sync(0xffffffffu, cm, 1));
        float mnew = fmaxf(m, cm);
        float resc = __expf(m - mnew);
        den *= resc; acc *= resc;
        m = mnew;
        float wr = __expf(sq - m);   // dummies: exp(-1e30 - m) == 0
        float dl = wr;
        dl += __shfl_xor_sync(0xffffffffu, dl, 16);
        dl += __shfl_xor_sync(0xffffffffu, dl, 8);
        dl += __shfl_xor_sync(0xffffffffu, dl, 4);
        dl += __shfl_xor_sync(0xffffffffu, dl, 2);
        dl += __shfl_xor_sync(0xffffffffu, dl, 1);
        den += dl;

        // --- pass 3: aggregation ---
        for (int jj = 0; jj < cnt; jj++) {
            float wj = __shfl_sync(0xffffffffu, wr, jj);
            float hs = hb[es_s[jj].y * HC + t];
            acc += wj * hs;
        }
        __syncthreads();
    }

    float v = acc / (den + 1e-16f);
    float o = (v > 0.f) ? v : expm1f(v);
    g_xflat[(size_t)b * FLATd + n * HC + t] = o;
}

// ---------------- fc1 via mma.sync bf16 3-split ----------------
#define FA_HI 0
#define FA_LO 10240
#define FB_HI 20480
#define FB_LO 25600

__global__ void __launch_bounds__(256) k_fc1_mma(const float* __restrict__ wq) {
    __shared__ __align__(16) unsigned char smbuf[30720];
    const uint32_t sb = smem_u32(smbuf);
    const int tid = threadIdx.x;
    const int wid = tid >> 5, lane = tid & 31;
    const int wm = wid & 3, wn = wid >> 2;
    const int ntile = blockIdx.x << 6;
    const int k0 = blockIdx.y << 9;

    float acc[2][4][4];
#pragma unroll
    for (int a = 0; a < 2; a++)
#pragma unroll
        for (int b = 0; b < 4; b++)
#pragma unroll
            for (int c = 0; c < 4; c++) acc[a][b][c] = 0.f;

    const uint32_t aAddrBase = sb + (uint32_t)((wm * 32 + (lane & 15)) * 80
                               + ((lane >> 4) & 1) * 16);
    const uint32_t bAddrBase = sb + (uint32_t)((wn * 32 + (lane & 7) + ((lane >> 4) ? 8 : 0)) * 80
                               + ((lane >> 3) & 1) * 16);

    float4 fA[4], fB[2];
#pragma unroll
    for (int r = 0; r < 4; r++) {
        int i = tid + r * 256;
        fA[r] = *(const float4*)(g_xflat + (size_t)(i >> 3) * FLATd + k0 + (i & 7) * 4);
    }
#pragma unroll
    for (int r = 0; r < 2; r++) {
        int i = tid + r * 256;
        fB[r] = *(const float4*)(wq + (size_t)(ntile + (i >> 3)) * FLATd + k0 + (i & 7) * 4);
    }

    for (int it = 0; it < 16; it++) {
#pragma unroll
        for (int r = 0; r < 4; r++) {
            int i = tid + r * 256;
            uint32_t addr = (uint32_t)((i >> 3) * 80 + (i & 7) * 8);
            uint32_t h0, l0, h1, l1;
            cvtpair(fA[r].x, fA[r].y, h0, l0);
            cvtpair(fA[r].z, fA[r].w, h1, l1);
            sts_v2(sb + FA_HI + addr, h0, h1);
            sts_v2(sb + FA_LO + addr, l0, l1);
        }
#pragma unroll
        for (int r = 0; r < 2; r++) {
            int i = tid + r * 256;
            uint32_t addr = (uint32_t)((i >> 3) * 80 + (i & 7) * 8);
            uint32_t h0, l0, h1, l1;
            cvtpair(fB[r].x, fB[r].y, h0, l0);
            cvtpair(fB[r].z, fB[r].w, h1, l1);
            sts_v2(sb + FB_HI + addr, h0, h1);
            sts_v2(sb + FB_LO + addr, l0, l1);
        }
        __syncthreads();

        if (it < 15) {
            int knext = k0 + (it + 1) * 32;
#pragma unroll
            for (int r = 0; r < 4; r++) {
                int i = tid + r * 256;
                fA[r] = *(const float4*)(g_xflat + (size_t)(i >> 3) * FLATd + knext + (i & 7) * 4);
            }
#pragma unroll
            for (int r = 0; r < 2; r++) {
                int i = tid + r * 256;
                fB[r] = *(const float4*)(wq + (size_t)(ntile + (i >> 3)) * FLATd + knext + (i & 7) * 4);
            }
        }

#pragma unroll
        for (int ks = 0; ks < 2; ks++) {
            uint32_t Ah[2][4], Al[2][4], Bh[2][4], Bl[2][4];
#pragma unroll
            for (int mt = 0; mt < 2; mt++) {
                uint32_t a = aAddrBase + (uint32_t)(mt * 16 * 80 + ks * 32);
                ldm_x4(Ah[mt], a + FA_HI);
                ldm_x4(Al[mt], a + FA_LO);
            }
#pragma unroll
            for (int np = 0; np < 2; np++) {
                uint32_t a = bAddrBase + (uint32_t)(np * 16 * 80 + ks * 32);
                ldm_x4(Bh[np], a + FB_HI);
                ldm_x4(Bl[np], a + FB_LO);
            }
#pragma unroll
            for (int mt = 0; mt < 2; mt++)
#pragma unroll
                for (int np = 0; np < 2; np++)
#pragma unroll
                    for (int hf = 0; hf < 2; hf++) {
                        int nt = np * 2 + hf;
                        mma_bf16(acc[mt][nt], Ah[mt], Bh[np][hf * 2], Bh[np][hf * 2 + 1]);
                        mma_bf16(acc[mt][nt], Ah[mt], Bl[np][hf * 2], Bl[np][hf * 2 + 1]);
                        mma_bf16(acc[mt][nt], Al[mt], Bh[np][hf * 2], Bh[np][hf * 2 + 1]);
                    }
        }
        __syncthreads();
    }

    float* outp = g_h1part + (size_t)blockIdx.y * (Bsz * HIDd);
#pragma unroll
    for (int mt = 0; mt < 2; mt++) {
        int rrow = wm * 32 + mt * 16 + (lane >> 2);
#pragma unroll
        for (int nt = 0; nt < 4; nt++) {
            int ccol = ntile + wn * 32 + nt * 8 + (lane & 3) * 2;
            *(float2*)&outp[(size_t)rrow * HIDd + ccol] =
                make_float2(acc[mt][nt][0], acc[mt][nt][1]);
            *(float2*)&outp[(size_t)(rrow + 8) * HIDd + ccol] =
                make_float2(acc[mt][nt][2], acc[mt][nt][3]);
        }
    }
}

// ---------------- split-K reduce + bias + BN + ReLU ----------------
__global__ void k_bnrelu(const float* __restrict__ fb,
                         const float* __restrict__ g,
                         const float* __restrict__ beta) {
    int gid = blockIdx.x * 256 + threadIdx.x;
    float s = 0.f;
#pragma unroll
    for (int p = 0; p < SPLITK; p++) s += g_h1part[(size_t)p * (Bsz * HIDd) + gid];
    int o = gid & (HIDd - 1);
    float val = (s + fb[o]) * (g[o] * rsqrtf(1.f + 1e-5f)) + beta[o];
    g_h1[gid] = fmaxf(val, 0.f);
}

// ---------------- fc2 ----------------
__global__ void k_fc2(const float* __restrict__ w2, const float* __restrict__ b2,
                      float* __restrict__ out) {
    int b = blockIdx.x, tid = threadIdx.x;
    float a0 = 0.f, a1 = 0.f;
    for (int o = tid; o < HIDd; o += 256) {
        float h = g_h1[(size_t)b * HIDd + o];
        a0 += h * w2[o];
        a1 += h * w2[HIDd + o];
    }
    __shared__ float r0[256], r1[256];
    r0[tid] = a0; r1[tid] = a1;
    __syncthreads();
    for (int s = 128; s > 0; s >>= 1) {
        if (tid < s) { r0[tid] += r0[tid + s]; r1[tid] += r1[tid + s]; }
        __syncthreads();
    }
    if (tid == 0) {
        out[b * 2 + 0] = r0[0] + b2[0];
        out[b * 2 + 1] = r1[0] + b2[1];
    }
}

extern "C" void kernel_launch(void* const* d_in, const int* in_sizes, int n_in,
                              void* d_out, int out_size) {
    const float* x       = (const float*)d_in[0];
    const int*   ei      = (const int*)  d_in[1];
    const float* eattr   = (const float*)d_in[2];
    const float* tcn_w   = (const float*)d_in[3];
    const float* tcn_b   = (const float*)d_in[4];
    const float* lin_l_w = (const float*)d_in[5];
    const float* lin_l_b = (const float*)d_in[6];
    const float* lin_e_w = (const float*)d_in[7];
    const float* lin_e_b = (const float*)d_in[8];
    const float* att     = (const float*)d_in[9];
    const float* fc1_w   = (const float*)d_in[10];
    const float* fc1_b   = (const float*)d_in[11];
    const float* bn_g    = (const float*)d_in[12];
    const float* bn_b    = (const float*)d_in[13];
    const float* fc2_w   = (const float*)d_in[14];
    const float* fc2_b   = (const float*)d_in[15];
    float* out = (float*)d_out;

    k_csr<<<1, 512>>>(ei);
    k_tcn<<<dim3(4, Bsz), 128>>>(x, tcn_w, tcn_b);
    k_linl<<<dim3(2, Bsz), 256>>>(lin_l_w, lin_l_b);
    k_gat<<<dim3(NN, Bsz), 128>>>(eattr, lin_e_w, lin_e_b, att);
    k_fc1_mma<<<dim3(32, SPLITK), 256>>>(fc1_w);
    k_bnrelu<<<(Bsz * HIDd) / 256, 256>>>(fc1_b, bn_g, bn_b);
    k_fc2<<<Bsz, 256>>>(fc2_w, fc2_b, out);
}

// round 9
// speedup vs baseline: 1.1915x; 1.1915x over previous
#include <cuda_runtime.h>
#include <cuda_bf16.h>
#include <math.h>
#include <stdint.h>

#define Bsz   128
#define Wd    128
#define FIN   64
#define NN    64
#define EE    4096
#define EDd   16
#define HC    128
#define FLATd 8192
#define HIDd  2048
#define SPLITK 16

// ---------------- scratch ----------------
__device__ __align__(128) float g_xg[Bsz * NN * Wd];
__device__ __align__(128) float g_h[Bsz * NN * HC];
__device__ __align__(128) float g_xflat[Bsz * FLATd];
__device__ __align__(128) float g_h1part[SPLITK * Bsz * HIDd];
__device__ __align__(128) float g_h1[Bsz * HIDd];
__device__ __align__(128) float g_score[Bsz * EE * 4];   // [b][e][h]
__device__ int  g_csr_off[NN + 1];
__device__ int2 g_csr_es[EE];

// ---------------- helpers ----------------
__device__ __forceinline__ uint32_t smem_u32(const void* p) {
    uint32_t a;
    asm("{ .reg .u64 t; cvta.to.shared.u64 t, %1; cvt.u32.u64 %0, t; }" : "=r"(a) : "l"(p));
    return a;
}
__device__ __forceinline__ void ldm_x4(uint32_t (&r)[4], uint32_t addr) {
    asm volatile("ldmatrix.sync.aligned.m8n8.x4.shared.b16 {%0,%1,%2,%3}, [%4];"
        : "=r"(r[0]), "=r"(r[1]), "=r"(r[2]), "=r"(r[3]) : "r"(addr));
}
__device__ __forceinline__ void mma_bf16(float (&d)[4], const uint32_t (&a)[4],
                                         uint32_t b0, uint32_t b1) {
    asm volatile(
        "mma.sync.aligned.m16n8k16.row.col.f32.bf16.bf16.f32 "
        "{%0,%1,%2,%3}, {%4,%5,%6,%7}, {%8,%9}, {%0,%1,%2,%3};"
        : "+f"(d[0]), "+f"(d[1]), "+f"(d[2]), "+f"(d[3])
        : "r"(a[0]), "r"(a[1]), "r"(a[2]), "r"(a[3]), "r"(b0), "r"(b1));
}
__device__ __forceinline__ void cvtpair(float a, float b, uint32_t& hi, uint32_t& lo) {
    __nv_bfloat16 ha = __float2bfloat16(a), hb2 = __float2bfloat16(b);
    float ra = a - __bfloat162float(ha), rb = b - __bfloat162float(hb2);
    __nv_bfloat16 la = __float2bfloat16(ra), lb = __float2bfloat16(rb);
    hi = (uint32_t)__bfloat16_as_ushort(ha) | ((uint32_t)__bfloat16_as_ushort(hb2) << 16);
    lo = (uint32_t)__bfloat16_as_ushort(la) | ((uint32_t)__bfloat16_as_ushort(lb) << 16);
}
__device__ __forceinline__ void sts_v2(uint32_t addr, uint32_t x, uint32_t y) {
    asm volatile("st.shared.v2.b32 [%0], {%1,%2};" :: "r"(addr), "r"(x), "r"(y) : "memory");
}

// ---------------- CSR build ----------------
__global__ void k_csr(const int* __restrict__ ei) {
    __shared__ int cnt[NN];
    __shared__ int off[NN + 1];
    __shared__ int cur[NN];
    int tid = threadIdx.x;
    if (tid < NN) cnt[tid] = 0;
    __syncthreads();
    for (int e = tid; e < EE; e += blockDim.x)
        atomicAdd(&cnt[ei[EE + e]], 1);
    __syncthreads();
    if (tid == 0) {
        int run = 0;
        for (int k = 0; k < NN; k++) { off[k] = run; cur[k] = run; run += cnt[k]; }
        off[NN] = run;
    }
    __syncthreads();
    for (int e = tid; e < EE; e += blockDim.x) {
        int d = ei[EE + e];
        int pos = atomicAdd(&cur[d], 1);
        g_csr_es[pos] = make_int2(e, ei[e]);
    }
    if (tid <= NN) g_csr_off[tid] = off[tid];
}

// ---------------- TCN conv1d(k=3,pad=1) ----------------
__global__ void k_tcn(const float* __restrict__ x,
                      const float* __restrict__ tw,
                      const float* __restrict__ tb) {
    __shared__ float xs[FIN * 129];
    __shared__ float sw[16 * 192];
    int b = blockIdx.y, nc = blockIdx.x;
    int tid = threadIdx.x;
    const float* xb = x + (size_t)b * Wd * FIN;
    for (int idx = tid; idx < Wd * FIN; idx += 128) {
        int w = idx >> 6, i = idx & 63;
        xs[i * 129 + w] = xb[idx];
    }
    for (int idx = tid; idx < 16 * 192; idx += 128)
        sw[idx] = tw[nc * 16 * 192 + idx];
    __syncthreads();
    int w = tid;
    float acc[16];
#pragma unroll
    for (int nl = 0; nl < 16; nl++) acc[nl] = tb[nc * 16 + nl];
    for (int i = 0; i < FIN; i++) {
        float x0 = xs[i * 129 + w];
        float xm = (w > 0)   ? xs[i * 129 + w - 1] : 0.f;
        float xp = (w < 127) ? xs[i * 129 + w + 1] : 0.f;
#pragma unroll
        for (int nl = 0; nl < 16; nl++) {
            const float* wp = &sw[nl * 192 + i * 3];
            acc[nl] += xm * wp[0] + x0 * wp[1] + xp * wp[2];
        }
    }
#pragma unroll
    for (int nl = 0; nl < 16; nl++)
        g_xg[((size_t)b * NN + nc * 16 + nl) * Wd + w] = acc[nl];
}

// ---------------- lin_l projection ----------------
__global__ void k_linl(const float* __restrict__ lw, const float* __restrict__ lb) {
    __shared__ float xs[NN * 129];
    __shared__ float ws[64 * 33];
    int b = blockIdx.y, oc = blockIdx.x;
    int tid = threadIdx.x;
    for (int idx = tid; idx < NN * Wd; idx += 256) {
        int n = idx >> 7, w = idx & 127;
        xs[n * 129 + w] = g_xg[(size_t)b * NN * Wd + idx];
    }
    int tx = tid & 15, ty = tid >> 4;
    float acc[4][4];
#pragma unroll
    for (int i = 0; i < 4; i++)
#pragma unroll
        for (int j = 0; j < 4; j++) acc[i][j] = 0.f;
    for (int wc = 0; wc < 4; wc++) {
        __syncthreads();
        for (int idx = tid; idx < 64 * 32; idx += 256) {
            int ol = idx >> 5, wl = idx & 31;
            ws[ol * 33 + wl] = lw[(oc * 64 + ol) * Wd + wc * 32 + wl];
        }
        __syncthreads();
#pragma unroll 4
        for (int wl = 0; wl < 32; wl++) {
            float a[4], bb[4];
#pragma unroll
            for (int j = 0; j < 4; j++) a[j]  = xs[(ty * 4 + j) * 129 + wc * 32 + wl];
#pragma unroll
            for (int j = 0; j < 4; j++) bb[j] = ws[(tx * 4 + j) * 33 + wl];
#pragma unroll
            for (int i = 0; i < 4; i++)
#pragma unroll
                for (int j = 0; j < 4; j++) acc[i][j] += a[i] * bb[j];
        }
    }
#pragma unroll
    for (int i = 0; i < 4; i++)
#pragma unroll
        for (int j = 0; j < 4; j++) {
            int n = ty * 4 + i, o = oc * 64 + tx * 4 + j;
            g_h[((size_t)b * NN + n) * HC + o] = acc[i][j] + lb[o];
        }
}

// ---------------- k_score: per 32-edge tile, mma edge projection + score epilogue ----------------
// grid (EE/32, Bsz), 128 threads. Writes g_score[b][e][h].
__global__ void __launch_bounds__(128) k_score(const int* __restrict__ ei,
                       const float* __restrict__ eattr,
                       const float* __restrict__ lew,
                       const float* __restrict__ leb,
                       const float* __restrict__ att) {
    __shared__ uint32_t bfrag[2][4][2][32];    // [hi/lo][ntile][reg][lane]
    __shared__ float    ev_s[32 * 133];        // [edge][ch + pad5] ~17KB
    __shared__ int      src_s[32], dst_s[32];

    int e0 = blockIdx.x << 5, b = blockIdx.y;
    int t = threadIdx.x, lane = t & 31, wd = t >> 5;
    int g = lane >> 2, tq = lane & 3;

    // A fragments: warp's 32 channels of lin_e_w, bf16 hi/lo (from R8, validated)
    uint32_t Ah[2][4], Al[2][4];
#pragma unroll
    for (int mt = 0; mt < 2; mt++) {
        int ch0 = wd * 32 + mt * 16 + g;
        const float* wr0 = lew + ch0 * EDd;
        const float* wr1 = lew + (ch0 + 8) * EDd;
        float2 p0 = *(const float2*)(wr0 + 2 * tq);
        float2 p1 = *(const float2*)(wr1 + 2 * tq);
        float2 p2 = *(const float2*)(wr0 + 2 * tq + 8);
        float2 p3 = *(const float2*)(wr1 + 2 * tq + 8);
        cvtpair(p0.x, p0.y, Ah[mt][0], Al[mt][0]);
        cvtpair(p1.x, p1.y, Ah[mt][1], Al[mt][1]);
        cvtpair(p2.x, p2.y, Ah[mt][2], Al[mt][2]);
        cvtpair(p3.x, p3.y, Ah[mt][3], Al[mt][3]);
    }

    if (t < 32) {
        src_s[t] = ei[e0 + t];
        dst_s[t] = ei[EE + e0 + t];
    }
    // stage ea -> bf16 hi/lo B-fragments (coalesced: 32 consecutive edges)
    {
        int j = t >> 2, q = t & 3;
        const float* row = eattr + (size_t)b * EE * EDd + (size_t)(e0 + j) * EDd;
        float4 ea4 = *(const float4*)(row + q * 4);
        uint32_t h0, l0, h1, l1;
        cvtpair(ea4.x, ea4.y, h0, l0);
        cvtpair(ea4.z, ea4.w, h1, l1);
        int nt = j >> 3, reg = q >> 1;
        int lpos = (j & 7) * 4 + (q & 1) * 2;
        bfrag[0][nt][reg][lpos] = h0; bfrag[0][nt][reg][lpos + 1] = h1;
        bfrag[1][nt][reg][lpos] = l0; bfrag[1][nt][reg][lpos + 1] = l1;
    }
    __syncthreads();

    // mma: ev[e, ch] for this warp's channels (3-term bf16 split)
#pragma unroll
    for (int nt = 0; nt < 4; nt++) {
        uint32_t b0h = bfrag[0][nt][0][lane], b1h = bfrag[0][nt][1][lane];
        uint32_t b0l = bfrag[1][nt][0][lane], b1l = bfrag[1][nt][1][lane];
#pragma unroll
        for (int mt = 0; mt < 2; mt++) {
            float a4[4] = {0.f, 0.f, 0.f, 0.f};
            mma_bf16(a4, Ah[mt], b0h, b1h);
            mma_bf16(a4, Ah[mt], b0l, b1l);
            mma_bf16(a4, Al[mt], b0h, b1h);
            int ch = wd * 32 + mt * 16 + g;
            int el = nt * 8 + 2 * tq;
            ev_s[el * 133 + ch]           = a4[0];
            ev_s[(el + 1) * 133 + ch]     = a4[1];
            ev_s[el * 133 + ch + 8]       = a4[2];
            ev_s[(el + 1) * 133 + ch + 8] = a4[3];
        }
    }
    __syncwarp();

    // epilogue: products in-place (thread t = channel t, own-warp data only)
    float ebt = leb[t], att_t = att[t];
    const float* hb = g_h + (size_t)b * NN * HC;
    for (int jj = 0; jj < 32; jj++) {
        float hd = hb[dst_s[jj] * HC + t];
        float hs = hb[src_s[jj] * HC + t];
        float z = hd + hs + ebt + ev_s[jj * 133 + t];
        ev_s[jj * 133 + t] = fmaxf(z, 0.01f * z) * att_t;
    }
    __syncwarp();

    // transposed reduce: lane sums edge `lane` over warp's 32 channels
    {
        const float* rp = &ev_s[lane * 133 + wd * 32];
        float s0 = 0.f, s1 = 0.f, s2 = 0.f, s3 = 0.f;
#pragma unroll
        for (int c4 = 0; c4 < 8; c4++) {
            s0 += rp[c4 * 4 + 0];
            s1 += rp[c4 * 4 + 1];
            s2 += rp[c4 * 4 + 2];
            s3 += rp[c4 * 4 + 3];
        }
        g_score[((size_t)b * EE + e0 + lane) * 4 + wd] = (s0 + s1) + (s2 + s3);
    }
}

// ---------------- k_agg: per-node softmax + aggregation over materialized scores ----------------
__global__ void __launch_bounds__(128) k_agg() {
    __shared__ int2   es_s[128];
    __shared__ float4 sc_s[128];
    __shared__ float  alpha_s[4][128];
    int n = blockIdx.x, b = blockIdx.y;
    int t = threadIdx.x, lane = t & 31, h = t >> 5;
    const float* hb = g_h + (size_t)b * NN * HC;

    int beg = g_csr_off[n], end = g_csr_off[n + 1];
    int deg = end - beg;
    const int2* lst = g_csr_es + beg;

    float m = -1e30f, den = 0.f, acc = 0.f;

    for (int base = 0; base < deg; base += 128) {
        int cnt = min(128, deg - base);
        if (t < cnt) {
            int2 p = lst[base + t];
            es_s[t] = p;
            sc_s[t] = *(const float4*)&g_score[((size_t)b * EE + p.x) * 4];
        }
        __syncthreads();

        // per-warp online softmax (lane covers up to 4 edges)
        float sl[4];
#pragma unroll
        for (int r = 0; r < 4; r++) {
            int jj = lane + r * 32;
            sl[r] = (jj < cnt) ? ((const float*)&sc_s[jj])[h] : -1e30f;
        }
        float cm = fmaxf(fmaxf(sl[0], sl[1]), fmaxf(sl[2], sl[3]));
        cm = fmaxf(cm, __shfl_xor_sync(0xffffffffu, cm, 16));
        cm = fmaxf(cm, __shfl_xor_sync(0xffffffffu, cm, 8));
        cm = fmaxf(cm, __shfl_xor_sync(0xffffffffu, cm, 4));
        cm = fmaxf(cm, __shfl_xor_sync(0xffffffffu, cm, 2));
        cm = fmaxf(cm, __shfl_xor_sync(0xffffffffu, cm, 1));
        float mnew = fmaxf(m, cm);
        float resc = __expf(m - mnew);
        den *= resc; acc *= resc;
        m = mnew;
        float wsum = 0.f;
#pragma unroll
        for (int r = 0; r < 4; r++) {
            float wr = __expf(sl[r] - m);
            wsum += wr;
            alpha_s[h][lane + r * 32] = wr;
        }
        wsum += __shfl_xor_sync(0xffffffffu, wsum, 16);
        wsum += __shfl_xor_sync(0xffffffffu, wsum, 8);
        wsum += __shfl_xor_sync(0xffffffffu, wsum, 4);
        wsum += __shfl_xor_sync(0xffffffffu, wsum, 2);
        wsum += __shfl_xor_sync(0xffffffffu, wsum, 1);
        den += wsum;
        __syncwarp();

        // aggregation: thread t = channel t
        for (int jj = 0; jj < cnt; jj++)
            acc += alpha_s[h][jj] * hb[es_s[jj].y * HC + t];
        __syncthreads();
    }

    float v = acc / (den + 1e-16f);
    float o = (v > 0.f) ? v : expm1f(v);
    g_xflat[(size_t)b * FLATd + n * HC + t] = o;
}

// ---------------- fc1 via mma.sync bf16 3-split ----------------
#define FA_HI 0
#define FA_LO 10240
#define FB_HI 20480
#define FB_LO 25600

__global__ void __launch_bounds__(256) k_fc1_mma(const float* __restrict__ wq) {
    __shared__ __align__(16) unsigned char smbuf[30720];
    const uint32_t sb = smem_u32(smbuf);
    const int tid = threadIdx.x;
    const int wid = tid >> 5, lane = tid & 31;
    const int wm = wid & 3, wn = wid >> 2;
    const int ntile = blockIdx.x << 6;
    const int k0 = blockIdx.y << 9;

    float acc[2][4][4];
#pragma unroll
    for (int a = 0; a < 2; a++)
#pragma unroll
        for (int b = 0; b < 4; b++)
#pragma unroll
            for (int c = 0; c < 4; c++) acc[a][b][c] = 0.f;

    const uint32_t aAddrBase = sb + (uint32_t)((wm * 32 + (lane & 15)) * 80
                               + ((lane >> 4) & 1) * 16);
    const uint32_t bAddrBase = sb + (uint32_t)((wn * 32 + (lane & 7) + ((lane >> 4) ? 8 : 0)) * 80
                               + ((lane >> 3) & 1) * 16);

    float4 fA[4], fB[2];
#pragma unroll
    for (int r = 0; r < 4; r++) {
        int i = tid + r * 256;
        fA[r] = *(const float4*)(g_xflat + (size_t)(i >> 3) * FLATd + k0 + (i & 7) * 4);
    }
#pragma unroll
    for (int r = 0; r < 2; r++) {
        int i = tid + r * 256;
        fB[r] = *(const float4*)(wq + (size_t)(ntile + (i >> 3)) * FLATd + k0 + (i & 7) * 4);
    }

    for (int it = 0; it < 16; it++) {
#pragma unroll
        for (int r = 0; r < 4; r++) {
            int i = tid + r * 256;
            uint32_t addr = (uint32_t)((i >> 3) * 80 + (i & 7) * 8);
            uint32_t h0, l0, h1, l1;
            cvtpair(fA[r].x, fA[r].y, h0, l0);
            cvtpair(fA[r].z, fA[r].w, h1, l1);
            sts_v2(sb + FA_HI + addr, h0, h1);
            sts_v2(sb + FA_LO + addr, l0, l1);
        }
#pragma unroll
        for (int r = 0; r < 2; r++) {
            int i = tid + r * 256;
            uint32_t addr = (uint32_t)((i >> 3) * 80 + (i & 7) * 8);
            uint32_t h0, l0, h1, l1;
            cvtpair(fB[r].x, fB[r].y, h0, l0);
            cvtpair(fB[r].z, fB[r].w, h1, l1);
            sts_v2(sb + FB_HI + addr, h0, h1);
            sts_v2(sb + FB_LO + addr, l0, l1);
        }
        __syncthreads();

        if (it < 15) {
            int knext = k0 + (it + 1) * 32;
#pragma unroll
            for (int r = 0; r < 4; r++) {
                int i = tid + r * 256;
                fA[r] = *(const float4*)(g_xflat + (size_t)(i >> 3) * FLATd + knext + (i & 7) * 4);
            }
#pragma unroll
            for (int r = 0; r < 2; r++) {
                int i = tid + r * 256;
                fB[r] = *(const float4*)(wq + (size_t)(ntile + (i >> 3)) * FLATd + knext + (i & 7) * 4);
            }
        }

#pragma unroll
        for (int ks = 0; ks < 2; ks++) {
            uint32_t Ah[2][4], Al[2][4], Bh[2][4], Bl[2][4];
#pragma unroll
            for (int mt = 0; mt < 2; mt++) {
                uint32_t a = aAddrBase + (uint32_t)(mt * 16 * 80 + ks * 32);
                ldm_x4(Ah[mt], a + FA_HI);
                ldm_x4(Al[mt], a + FA_LO);
            }
#pragma unroll
            for (int np = 0; np < 2; np++) {
                uint32_t a = bAddrBase + (uint32_t)(np * 16 * 80 + ks * 32);
                ldm_x4(Bh[np], a + FB_HI);
                ldm_x4(Bl[np], a + FB_LO);
            }
#pragma unroll
            for (int mt = 0; mt < 2; mt++)
#pragma unroll
                for (int np = 0; np < 2; np++)
#pragma unroll
                    for (int hf = 0; hf < 2; hf++) {
                        int nt = np * 2 + hf;
                        mma_bf16(acc[mt][nt], Ah[mt], Bh[np][hf * 2], Bh[np][hf * 2 + 1]);
                        mma_bf16(acc[mt][nt], Ah[mt], Bl[np][hf * 2], Bl[np][hf * 2 + 1]);
                        mma_bf16(acc[mt][nt], Al[mt], Bh[np][hf * 2], Bh[np][hf * 2 + 1]);
                    }
        }
        __syncthreads();
    }

    float* outp = g_h1part + (size_t)blockIdx.y * (Bsz * HIDd);
#pragma unroll
    for (int mt = 0; mt < 2; mt++) {
        int rrow = wm * 32 + mt * 16 + (lane >> 2);
#pragma unroll
        for (int nt = 0; nt < 4; nt++) {
            int ccol = ntile + wn * 32 + nt * 8 + (lane & 3) * 2;
            *(float2*)&outp[(size_t)rrow * HIDd + ccol] =
                make_float2(acc[mt][nt][0], acc[mt][nt][1]);
            *(float2*)&outp[(size_t)(rrow + 8) * HIDd + ccol] =
                make_float2(acc[mt][nt][2], acc[mt][nt][3]);
        }
    }
}

// ---------------- split-K reduce + bias + BN + ReLU ----------------
__global__ void k_bnrelu(const float* __restrict__ fb,
                         const float* __restrict__ g,
                         const float* __restrict__ beta) {
    int gid = blockIdx.x * 256 + threadIdx.x;
    float s = 0.f;
#pragma unroll
    for (int p = 0; p < SPLITK; p++) s += g_h1part[(size_t)p * (Bsz * HIDd) + gid];
    int o = gid & (HIDd - 1);
    float val = (s + fb[o]) * (g[o] * rsqrtf(1.f + 1e-5f)) + beta[o];
    g_h1[gid] = fmaxf(val, 0.f);
}

// ---------------- fc2 ----------------
__global__ void k_fc2(const float* __restrict__ w2, const float* __restrict__ b2,
                      float* __restrict__ out) {
    int b = blockIdx.x, tid = threadIdx.x;
    float a0 = 0.f, a1 = 0.f;
    for (int o = tid; o < HIDd; o += 256) {
        float h = g_h1[(size_t)b * HIDd + o];
        a0 += h * w2[o];
        a1 += h * w2[HIDd + o];
    }
    __shared__ float r0[256], r1[256];
    r0[tid] = a0; r1[tid] = a1;
    __syncthreads();
    for (int s = 128; s > 0; s >>= 1) {
        if (tid < s) { r0[tid] += r0[tid + s]; r1[tid] += r1[tid + s]; }
        __syncthreads();
    }
    if (tid == 0) {
        out[b * 2 + 0] = r0[0] + b2[0];
        out[b * 2 + 1] = r1[0] + b2[1];
    }
}

extern "C" void kernel_launch(void* const* d_in, const int* in_sizes, int n_in,
                              void* d_out, int out_size) {
    const float* x       = (const float*)d_in[0];
    const int*   ei      = (const int*)  d_in[1];
    const float* eattr   = (const float*)d_in[2];
    const float* tcn_w   = (const float*)d_in[3];
    const float* tcn_b   = (const float*)d_in[4];
    const float* lin_l_w = (const float*)d_in[5];
    const float* lin_l_b = (const float*)d_in[6];
    const float* lin_e_w = (const float*)d_in[7];
    const float* lin_e_b = (const float*)d_in[8];
    const float* att     = (const float*)d_in[9];
    const float* fc1_w   = (const float*)d_in[10];
    const float* fc1_b   = (const float*)d_in[11];
    const float* bn_g    = (const float*)d_in[12];
    const float* bn_b    = (const float*)d_in[13];
    const float* fc2_w   = (const float*)d_in[14];
    const float* fc2_b   = (const float*)d_in[15];
    float* out = (float*)d_out;

    k_csr<<<1, 512>>>(ei);
    k_tcn<<<dim3(4, Bsz), 128>>>(x, tcn_w, tcn_b);
    k_linl<<<dim3(2, Bsz), 256>>>(lin_l_w, lin_l_b);
    k_score<<<dim3(EE / 32, Bsz), 128>>>(ei, eattr, lin_e_w, lin_e_b, att);
    k_agg<<<dim3(NN, Bsz), 128>>>();
    k_fc1_mma<<<dim3(32, SPLITK), 256>>>(fc1_w);
    k_bnrelu<<<(Bsz * HIDd) / 256, 256>>>(fc1_b, bn_g, bn_b);
    k_fc2<<<Bsz, 256>>>(fc2_w, fc2_b, out);
}

// round 10
// speedup vs baseline: 1.3310x; 1.1170x over previous
#include <cuda_runtime.h>
#include <cuda_bf16.h>
#include <math.h>
#include <stdint.h>

#define Bsz   128
#define Wd    128
#define FIN   64
#define NN    64
#define EE    4096
#define EDd   16
#define HC    128
#define FLATd 8192
#define HIDd  2048
#define SPLITK 16
#define EVW   132   // ev_s row pitch (floats)

// ---------------- scratch ----------------
__device__ __align__(128) float g_xg[Bsz * NN * Wd];
__device__ __align__(128) float g_h[Bsz * NN * HC];
__device__ __align__(128) float g_xflat[Bsz * FLATd];
__device__ __align__(128) float g_h1part[SPLITK * Bsz * HIDd];
__device__ __align__(128) float g_h1[Bsz * HIDd];
__device__ __align__(128) float g_score[Bsz * EE * 4];   // [b][e][h]
__device__ int  g_csr_off[NN + 1];
__device__ int2 g_csr_es[EE];

// ---------------- helpers ----------------
__device__ __forceinline__ uint32_t smem_u32(const void* p) {
    uint32_t a;
    asm("{ .reg .u64 t; cvta.to.shared.u64 t, %1; cvt.u32.u64 %0, t; }" : "=r"(a) : "l"(p));
    return a;
}
__device__ __forceinline__ void ldm_x4(uint32_t (&r)[4], uint32_t addr) {
    asm volatile("ldmatrix.sync.aligned.m8n8.x4.shared.b16 {%0,%1,%2,%3}, [%4];"
        : "=r"(r[0]), "=r"(r[1]), "=r"(r[2]), "=r"(r[3]) : "r"(addr));
}
__device__ __forceinline__ void mma_bf16(float (&d)[4], const uint32_t (&a)[4],
                                         uint32_t b0, uint32_t b1) {
    asm volatile(
        "mma.sync.aligned.m16n8k16.row.col.f32.bf16.bf16.f32 "
        "{%0,%1,%2,%3}, {%4,%5,%6,%7}, {%8,%9}, {%0,%1,%2,%3};"
        : "+f"(d[0]), "+f"(d[1]), "+f"(d[2]), "+f"(d[3])
        : "r"(a[0]), "r"(a[1]), "r"(a[2]), "r"(a[3]), "r"(b0), "r"(b1));
}
__device__ __forceinline__ void cvtpair(float a, float b, uint32_t& hi, uint32_t& lo) {
    __nv_bfloat16 ha = __float2bfloat16(a), hb2 = __float2bfloat16(b);
    float ra = a - __bfloat162float(ha), rb = b - __bfloat162float(hb2);
    __nv_bfloat16 la = __float2bfloat16(ra), lb = __float2bfloat16(rb);
    hi = (uint32_t)__bfloat16_as_ushort(ha) | ((uint32_t)__bfloat16_as_ushort(hb2) << 16);
    lo = (uint32_t)__bfloat16_as_ushort(la) | ((uint32_t)__bfloat16_as_ushort(lb) << 16);
}
__device__ __forceinline__ void sts_v2(uint32_t addr, uint32_t x, uint32_t y) {
    asm volatile("st.shared.v2.b32 [%0], {%1,%2};" :: "r"(addr), "r"(x), "r"(y) : "memory");
}
// f32x2 packed ops (proven in R2-R4 builds)
typedef unsigned long long u64;
__device__ __forceinline__ u64 pkx2(float lo, float hi) {
    u64 r; asm("mov.b64 %0, {%1,%2};" : "=l"(r) : "f"(lo), "f"(hi)); return r;
}
__device__ __forceinline__ u64 addx2(u64 a, u64 b) {
    u64 d; asm("add.rn.f32x2 %0, %1, %2;" : "=l"(d) : "l"(a), "l"(b)); return d;
}
__device__ __forceinline__ u64 mulx2(u64 a, u64 b) {
    u64 d; asm("mul.rn.f32x2 %0, %1, %2;" : "=l"(d) : "l"(a), "l"(b)); return d;
}
__device__ __forceinline__ u64 fmax2(u64 a, u64 b, u64 c) {
    u64 d; asm("fma.rn.f32x2 %0, %1, %2, %3;" : "=l"(d) : "l"(a), "l"(b), "l"(c)); return d;
}

// ---------------- CSR build ----------------
__global__ void k_csr(const int* __restrict__ ei) {
    __shared__ int cnt[NN];
    __shared__ int off[NN + 1];
    __shared__ int cur[NN];
    int tid = threadIdx.x;
    if (tid < NN) cnt[tid] = 0;
    __syncthreads();
    for (int e = tid; e < EE; e += blockDim.x)
        atomicAdd(&cnt[ei[EE + e]], 1);
    __syncthreads();
    if (tid == 0) {
        int run = 0;
        for (int k = 0; k < NN; k++) { off[k] = run; cur[k] = run; run += cnt[k]; }
        off[NN] = run;
    }
    __syncthreads();
    for (int e = tid; e < EE; e += blockDim.x) {
        int d = ei[EE + e];
        int pos = atomicAdd(&cur[d], 1);
        g_csr_es[pos] = make_int2(e, ei[e]);
    }
    if (tid <= NN) g_csr_off[tid] = off[tid];
}

// ---------------- TCN conv1d(k=3,pad=1) ----------------
__global__ void k_tcn(const float* __restrict__ x,
                      const float* __restrict__ tw,
                      const float* __restrict__ tb) {
    __shared__ float xs[FIN * 129];
    __shared__ float sw[16 * 192];
    int b = blockIdx.y, nc = blockIdx.x;
    int tid = threadIdx.x;
    const float* xb = x + (size_t)b * Wd * FIN;
    for (int idx = tid; idx < Wd * FIN; idx += 128) {
        int w = idx >> 6, i = idx & 63;
        xs[i * 129 + w] = xb[idx];
    }
    for (int idx = tid; idx < 16 * 192; idx += 128)
        sw[idx] = tw[nc * 16 * 192 + idx];
    __syncthreads();
    int w = tid;
    float acc[16];
#pragma unroll
    for (int nl = 0; nl < 16; nl++) acc[nl] = tb[nc * 16 + nl];
    for (int i = 0; i < FIN; i++) {
        float x0 = xs[i * 129 + w];
        float xm = (w > 0)   ? xs[i * 129 + w - 1] : 0.f;
        float xp = (w < 127) ? xs[i * 129 + w + 1] : 0.f;
#pragma unroll
        for (int nl = 0; nl < 16; nl++) {
            const float* wp = &sw[nl * 192 + i * 3];
            acc[nl] += xm * wp[0] + x0 * wp[1] + xp * wp[2];
        }
    }
#pragma unroll
    for (int nl = 0; nl < 16; nl++)
        g_xg[((size_t)b * NN + nc * 16 + nl) * Wd + w] = acc[nl];
}

// ---------------- lin_l projection ----------------
__global__ void k_linl(const float* __restrict__ lw, const float* __restrict__ lb) {
    __shared__ float xs[NN * 129];
    __shared__ float ws[64 * 33];
    int b = blockIdx.y, oc = blockIdx.x;
    int tid = threadIdx.x;
    for (int idx = tid; idx < NN * Wd; idx += 256) {
        int n = idx >> 7, w = idx & 127;
        xs[n * 129 + w] = g_xg[(size_t)b * NN * Wd + idx];
    }
    int tx = tid & 15, ty = tid >> 4;
    float acc[4][4];
#pragma unroll
    for (int i = 0; i < 4; i++)
#pragma unroll
        for (int j = 0; j < 4; j++) acc[i][j] = 0.f;
    for (int wc = 0; wc < 4; wc++) {
        __syncthreads();
        for (int idx = tid; idx < 64 * 32; idx += 256) {
            int ol = idx >> 5, wl = idx & 31;
            ws[ol * 33 + wl] = lw[(oc * 64 + ol) * Wd + wc * 32 + wl];
        }
        __syncthreads();
#pragma unroll 4
        for (int wl = 0; wl < 32; wl++) {
            float a[4], bb[4];
#pragma unroll
            for (int j = 0; j < 4; j++) a[j]  = xs[(ty * 4 + j) * 129 + wc * 32 + wl];
#pragma unroll
            for (int j = 0; j < 4; j++) bb[j] = ws[(tx * 4 + j) * 33 + wl];
#pragma unroll
            for (int i = 0; i < 4; i++)
#pragma unroll
                for (int j = 0; j < 4; j++) acc[i][j] += a[i] * bb[j];
        }
    }
#pragma unroll
    for (int i = 0; i < 4; i++)
#pragma unroll
        for (int j = 0; j < 4; j++) {
            int n = ty * 4 + i, o = oc * 64 + tx * 4 + j;
            g_h[((size_t)b * NN + n) * HC + o] = acc[i][j] + lb[o];
        }
}

// ---------------- k_score v2: 64 edges/block, mma projection + f32x2 epilogue ----------------
// grid (EE/64, Bsz), 256 threads (8 warps: wq = w&1 edge-half, wc = w>>1 channel-group)
__global__ void __launch_bounds__(256) k_score(const int* __restrict__ ei,
                       const float* __restrict__ eattr,
                       const float* __restrict__ lew,
                       const float* __restrict__ leb,
                       const float* __restrict__ att) {
    __shared__ uint32_t bfrag[2][2][4][2][32];       // [hi/lo][eh][nt][reg][lane] 4KB
    __shared__ __align__(16) float ev_s[64 * EVW];   // 33.8KB
    __shared__ int src_s[64], dst_s[64];

    int e0 = blockIdx.x << 6, b = blockIdx.y;
    int t = threadIdx.x, lane = t & 31, w = t >> 5;
    int wq = w & 1, wc = w >> 1;
    int g = lane >> 2, tq = lane & 3;

    // A fragments: channel group wc (32 channels), bf16 hi/lo
    uint32_t Ah[2][4], Al[2][4];
#pragma unroll
    for (int mt = 0; mt < 2; mt++) {
        int ch0 = wc * 32 + mt * 16 + g;
        const float* wr0 = lew + ch0 * EDd;
        const float* wr1 = lew + (ch0 + 8) * EDd;
        float2 p0 = *(const float2*)(wr0 + 2 * tq);
        float2 p1 = *(const float2*)(wr1 + 2 * tq);
        float2 p2 = *(const float2*)(wr0 + 2 * tq + 8);
        float2 p3 = *(const float2*)(wr1 + 2 * tq + 8);
        cvtpair(p0.x, p0.y, Ah[mt][0], Al[mt][0]);
        cvtpair(p1.x, p1.y, Ah[mt][1], Al[mt][1]);
        cvtpair(p2.x, p2.y, Ah[mt][2], Al[mt][2]);
        cvtpair(p3.x, p3.y, Ah[mt][3], Al[mt][3]);
    }

    if (t < 64) {
        src_s[t] = ei[e0 + t];
        dst_s[t] = ei[EE + e0 + t];
    }
    // stage ea -> bf16 hi/lo B-fragments (64 edges x 4 quads = 256 tasks)
    {
        int j = t >> 2, q = t & 3;
        const float* row = eattr + (size_t)b * EE * EDd + (size_t)(e0 + j) * EDd;
        float4 ea4 = *(const float4*)(row + q * 4);
        uint32_t h0, l0, h1, l1;
        cvtpair(ea4.x, ea4.y, h0, l0);
        cvtpair(ea4.z, ea4.w, h1, l1);
        int eh = j >> 5, j32 = j & 31;
        int nt = j32 >> 3, reg = q >> 1;
        int lpos = (j32 & 7) * 4 + (q & 1) * 2;
        bfrag[0][eh][nt][reg][lpos] = h0; bfrag[0][eh][nt][reg][lpos + 1] = h1;
        bfrag[1][eh][nt][reg][lpos] = l0; bfrag[1][eh][nt][reg][lpos + 1] = l1;
    }
    __syncthreads();

    // mma: warp computes its 32 channels for its 32 edges (3-term bf16 split)
#pragma unroll
    for (int nt = 0; nt < 4; nt++) {
        uint32_t b0h = bfrag[0][wq][nt][0][lane], b1h = bfrag[0][wq][nt][1][lane];
        uint32_t b0l = bfrag[1][wq][nt][0][lane], b1l = bfrag[1][wq][nt][1][lane];
#pragma unroll
        for (int mt = 0; mt < 2; mt++) {
            float a4[4] = {0.f, 0.f, 0.f, 0.f};
            mma_bf16(a4, Ah[mt], b0h, b1h);
            mma_bf16(a4, Ah[mt], b0l, b1l);
            mma_bf16(a4, Al[mt], b0h, b1h);
            int ch = wc * 32 + mt * 16 + g;
            int el = wq * 32 + nt * 8 + 2 * tq;
            ev_s[el * EVW + ch]           = a4[0];
            ev_s[(el + 1) * EVW + ch]     = a4[1];
            ev_s[el * EVW + ch + 8]       = a4[2];
            ev_s[(el + 1) * EVW + ch + 8] = a4[3];
        }
    }
    __syncthreads();

    // epilogue: f32x2 over channel pairs; thread = (ch pair pp, edge group g4)
    {
        int pp = t & 63, g4 = t >> 6;
        const float* hb = g_h + (size_t)b * NN * HC;
        u64 eb2  = *(const u64*)(leb + 2 * pp);
        u64 att2 = *(const u64*)(att + 2 * pp);
        const u64 C1 = pkx2(0.505f, 0.505f);
        const u64 C2 = pkx2(0.495f, 0.495f);
        const u64 MSK = 0x7FFFFFFF7FFFFFFFull;
#pragma unroll 4
        for (int r = 0; r < 16; r++) {
            int e = g4 * 16 + r;
            int s = src_s[e], d = dst_s[e];
            u64 hs2 = *(const u64*)(hb + s * HC + 2 * pp);
            u64 hd2 = *(const u64*)(hb + d * HC + 2 * pp);
            u64 ev2 = *(const u64*)&ev_s[e * EVW + 2 * pp];
            u64 z = addx2(addx2(hs2, hd2), addx2(ev2, eb2));
            u64 az; asm("and.b64 %0, %1, %2;" : "=l"(az) : "l"(z), "l"(MSK));
            u64 rr = fmax2(az, C2, mulx2(z, C1));     // leaky_relu
            *(u64*)&ev_s[e * EVW + 2 * pp] = mulx2(rr, att2);
        }
    }
    __syncthreads();

    // reduce: thread (e = t&63, h = t>>6) sums 32 channels -> score
    {
        int e = t & 63, h = t >> 6;
        const float* rp = &ev_s[e * EVW + h * 32];
        float s0 = 0.f, s1 = 0.f, s2 = 0.f, s3 = 0.f;
#pragma unroll
        for (int c4 = 0; c4 < 8; c4++) {
            float4 v = *(const float4*)(rp + c4 * 4);
            s0 += v.x; s1 += v.y; s2 += v.z; s3 += v.w;
        }
        g_score[((size_t)b * EE + e0 + e) * 4 + h] = (s0 + s1) + (s2 + s3);
    }
}

// ---------------- k_agg: per-node softmax + aggregation (ILP unroll) ----------------
__global__ void __launch_bounds__(128) k_agg() {
    __shared__ int2   es_s[128];
    __shared__ float4 sc_s[128];
    __shared__ float  alpha_s[4][128];
    int n = blockIdx.x, b = blockIdx.y;
    int t = threadIdx.x, lane = t & 31, h = t >> 5;
    const float* __restrict__ hb = g_h + (size_t)b * NN * HC;
    const float* __restrict__ hbt = hb + t;

    int beg = g_csr_off[n], end = g_csr_off[n + 1];
    int deg = end - beg;
    const int2* lst = g_csr_es + beg;

    float m = -1e30f, den = 0.f, acc = 0.f;

    for (int base = 0; base < deg; base += 128) {
        int cnt = min(128, deg - base);
        if (t < cnt) {
            int2 p = lst[base + t];
            es_s[t] = p;
            sc_s[t] = *(const float4*)&g_score[((size_t)b * EE + p.x) * 4];
        }
        __syncthreads();

        float sl[4];
#pragma unroll
        for (int r = 0; r < 4; r++) {
            int jj = lane + r * 32;
            sl[r] = (jj < cnt) ? ((const float*)&sc_s[jj])[h] : -1e30f;
        }
        float cm = fmaxf(fmaxf(sl[0], sl[1]), fmaxf(sl[2], sl[3]));
        cm = fmaxf(cm, __shfl_xor_sync(0xffffffffu, cm, 16));
        cm = fmaxf(cm, __shfl_xor_sync(0xffffffffu, cm, 8));
        cm = fmaxf(cm, __shfl_xor_sync(0xffffffffu, cm, 4));
        cm = fmaxf(cm, __shfl_xor_sync(0xffffffffu, cm, 2));
        cm = fmaxf(cm, __shfl_xor_sync(0xffffffffu, cm, 1));
        float mnew = fmaxf(m, cm);
        float resc = __expf(m - mnew);
        den *= resc; acc *= resc;
        m = mnew;
        float wsum = 0.f;
#pragma unroll
        for (int r = 0; r < 4; r++) {
            float wr = __expf(sl[r] - m);
            wsum += wr;
            alpha_s[h][lane + r * 32] = wr;
        }
        wsum += __shfl_xor_sync(0xffffffffu, wsum, 16);
        wsum += __shfl_xor_sync(0xffffffffu, wsum, 8);
        wsum += __shfl_xor_sync(0xffffffffu, wsum, 4);
        wsum += __shfl_xor_sync(0xffffffffu, wsum, 2);
        wsum += __shfl_xor_sync(0xffffffffu, wsum, 1);
        den += wsum;
        __syncwarp();

        // aggregation with 4 independent accumulators
        const float* __restrict__ al = alpha_s[h];
        float a0 = 0.f, a1 = 0.f, a2 = 0.f, a3 = 0.f;
        int jj = 0;
        for (; jj + 4 <= cnt; jj += 4) {
            a0 += al[jj]     * hbt[es_s[jj].y * HC];
            a1 += al[jj + 1] * hbt[es_s[jj + 1].y * HC];
            a2 += al[jj + 2] * hbt[es_s[jj + 2].y * HC];
            a3 += al[jj + 3] * hbt[es_s[jj + 3].y * HC];
        }
        for (; jj < cnt; jj++)
            a0 += al[jj] * hbt[es_s[jj].y * HC];
        acc += (a0 + a1) + (a2 + a3);
        __syncthreads();
    }

    float v = acc / (den + 1e-16f);
    float o = (v > 0.f) ? v : expm1f(v);
    g_xflat[(size_t)b * FLATd + n * HC + t] = o;
}

// ---------------- fc1 via mma.sync bf16 3-split ----------------
#define FA_HI 0
#define FA_LO 10240
#define FB_HI 20480
#define FB_LO 25600

__global__ void __launch_bounds__(256) k_fc1_mma(const float* __restrict__ wq) {
    __shared__ __align__(16) unsigned char smbuf[30720];
    const uint32_t sb = smem_u32(smbuf);
    const int tid = threadIdx.x;
    const int wid = tid >> 5, lane = tid & 31;
    const int wm = wid & 3, wn = wid >> 2;
    const int ntile = blockIdx.x << 6;
    const int k0 = blockIdx.y << 9;

    float acc[2][4][4];
#pragma unroll
    for (int a = 0; a < 2; a++)
#pragma unroll
        for (int b = 0; b < 4; b++)
#pragma unroll
            for (int c = 0; c < 4; c++) acc[a][b][c] = 0.f;

    const uint32_t aAddrBase = sb + (uint32_t)((wm * 32 + (lane & 15)) * 80
                               + ((lane >> 4) & 1) * 16);
    const uint32_t bAddrBase = sb + (uint32_t)((wn * 32 + (lane & 7) + ((lane >> 4) ? 8 : 0)) * 80
                               + ((lane >> 3) & 1) * 16);

    float4 fA[4], fB[2];
#pragma unroll
    for (int r = 0; r < 4; r++) {
        int i = tid + r * 256;
        fA[r] = *(const float4*)(g_xflat + (size_t)(i >> 3) * FLATd + k0 + (i & 7) * 4);
    }
#pragma unroll
    for (int r = 0; r < 2; r++) {
        int i = tid + r * 256;
        fB[r] = *(const float4*)(wq + (size_t)(ntile + (i >> 3)) * FLATd + k0 + (i & 7) * 4);
    }

    for (int it = 0; it < 16; it++) {
#pragma unroll
        for (int r = 0; r < 4; r++) {
            int i = tid + r * 256;
            uint32_t addr = (uint32_t)((i >> 3) * 80 + (i & 7) * 8);
            uint32_t h0, l0, h1, l1;
            cvtpair(fA[r].x, fA[r].y, h0, l0);
            cvtpair(fA[r].z, fA[r].w, h1, l1);
            sts_v2(sb + FA_HI + addr, h0, h1);
            sts_v2(sb + FA_LO + addr, l0, l1);
        }
#pragma unroll
        for (int r = 0; r < 2; r++) {
            int i = tid + r * 256;
            uint32_t addr = (uint32_t)((i >> 3) * 80 + (i & 7) * 8);
            uint32_t h0, l0, h1, l1;
            cvtpair(fB[r].x, fB[r].y, h0, l0);
            cvtpair(fB[r].z, fB[r].w, h1, l1);
            sts_v2(sb + FB_HI + addr, h0, h1);
            sts_v2(sb + FB_LO + addr, l0, l1);
        }
        __syncthreads();

        if (it < 15) {
            int knext = k0 + (it + 1) * 32;
#pragma unroll
            for (int r = 0; r < 4; r++) {
                int i = tid + r * 256;
                fA[r] = *(const float4*)(g_xflat + (size_t)(i >> 3) * FLATd + knext + (i & 7) * 4);
            }
#pragma unroll
            for (int r = 0; r < 2; r++) {
                int i = tid + r * 256;
                fB[r] = *(const float4*)(wq + (size_t)(ntile + (i >> 3)) * FLATd + knext + (i & 7) * 4);
            }
        }

#pragma unroll
        for (int ks = 0; ks < 2; ks++) {
            uint32_t Ah[2][4], Al[2][4], Bh[2][4], Bl[2][4];
#pragma unroll
            for (int mt = 0; mt < 2; mt++) {
                uint32_t a = aAddrBase + (uint32_t)(mt * 16 * 80 + ks * 32);
                ldm_x4(Ah[mt], a + FA_HI);
                ldm_x4(Al[mt], a + FA_LO);
            }
#pragma unroll
            for (int np = 0; np < 2; np++) {
                uint32_t a = bAddrBase + (uint32_t)(np * 16 * 80 + ks * 32);
                ldm_x4(Bh[np], a + FB_HI);
                ldm_x4(Bl[np], a + FB_LO);
            }
#pragma unroll
            for (int mt = 0; mt < 2; mt++)
#pragma unroll
                for (int np = 0; np < 2; np++)
#pragma unroll
                    for (int hf = 0; hf < 2; hf++) {
                        int nt = np * 2 + hf;
                        mma_bf16(acc[mt][nt], Ah[mt], Bh[np][hf * 2], Bh[np][hf * 2 + 1]);
                        mma_bf16(acc[mt][nt], Ah[mt], Bl[np][hf * 2], Bl[np][hf * 2 + 1]);
                        mma_bf16(acc[mt][nt], Al[mt], Bh[np][hf * 2], Bh[np][hf * 2 + 1]);
                    }
        }
        __syncthreads();
    }

    float* outp = g_h1part + (size_t)blockIdx.y * (Bsz * HIDd);
#pragma unroll
    for (int mt = 0; mt < 2; mt++) {
        int rrow = wm * 32 + mt * 16 + (lane >> 2);
#pragma unroll
        for (int nt = 0; nt < 4; nt++) {
            int ccol = ntile + wn * 32 + nt * 8 + (lane & 3) * 2;
            *(float2*)&outp[(size_t)rrow * HIDd + ccol] =
                make_float2(acc[mt][nt][0], acc[mt][nt][1]);
            *(float2*)&outp[(size_t)(rrow + 8) * HIDd + ccol] =
                make_float2(acc[mt][nt][2], acc[mt][nt][3]);
        }
    }
}

// ---------------- split-K reduce + bias + BN + ReLU ----------------
__global__ void k_bnrelu(const float* __restrict__ fb,
                         const float* __restrict__ g,
                         const float* __restrict__ beta) {
    int gid = blockIdx.x * 256 + threadIdx.x;
    float s = 0.f;
#pragma unroll
    for (int p = 0; p < SPLITK; p++) s += g_h1part[(size_t)p * (Bsz * HIDd) + gid];
    int o = gid & (HIDd - 1);
    float val = (s + fb[o]) * (g[o] * rsqrtf(1.f + 1e-5f)) + beta[o];
    g_h1[gid] = fmaxf(val, 0.f);
}

// ---------------- fc2 ----------------
__global__ void k_fc2(const float* __restrict__ w2, const float* __restrict__ b2,
                      float* __restrict__ out) {
    int b = blockIdx.x, tid = threadIdx.x;
    float a0 = 0.f, a1 = 0.f;
    for (int o = tid; o < HIDd; o += 256) {
        float h = g_h1[(size_t)b * HIDd + o];
        a0 += h * w2[o];
        a1 += h * w2[HIDd + o];
    }
    __shared__ float r0[256], r1[256];
    r0[tid] = a0; r1[tid] = a1;
    __syncthreads();
    for (int s = 128; s > 0; s >>= 1) {
        if (tid < s) { r0[tid] += r0[tid + s]; r1[tid] += r1[tid + s]; }
        __syncthreads();
    }
    if (tid == 0) {
        out[b * 2 + 0] = r0[0] + b2[0];
        out[b * 2 + 1] = r1[0] + b2[1];
    }
}

extern "C" void kernel_launch(void* const* d_in, const int* in_sizes, int n_in,
                              void* d_out, int out_size) {
    const float* x       = (const float*)d_in[0];
    const int*   ei      = (const int*)  d_in[1];
    const float* eattr   = (const float*)d_in[2];
    const float* tcn_w   = (const float*)d_in[3];
    const float* tcn_b   = (const float*)d_in[4];
    const float* lin_l_w = (const float*)d_in[5];
    const float* lin_l_b = (const float*)d_in[6];
    const float* lin_e_w = (const float*)d_in[7];
    const float* lin_e_b = (const float*)d_in[8];
    const float* att     = (const float*)d_in[9];
    const float* fc1_w   = (const float*)d_in[10];
    const float* fc1_b   = (const float*)d_in[11];
    const float* bn_g    = (const float*)d_in[12];
    const float* bn_b    = (const float*)d_in[13];
    const float* fc2_w   = (const float*)d_in[14];
    const float* fc2_b   = (const float*)d_in[15];
    float* out = (float*)d_out;

    k_csr<<<1, 512>>>(ei);
    k_tcn<<<dim3(4, Bsz), 128>>>(x, tcn_w, tcn_b);
    k_linl<<<dim3(2, Bsz), 256>>>(lin_l_w, lin_l_b);
    k_score<<<dim3(EE / 64, Bsz), 256>>>(ei, eattr, lin_e_w, lin_e_b, att);
    k_agg<<<dim3(NN, Bsz), 128>>>();
    k_fc1_mma<<<dim3(32, SPLITK), 256>>>(fc1_w);
    k_bnrelu<<<(Bsz * HIDd) / 256, 256>>>(fc1_b, bn_g, bn_b);
    k_fc2<<<Bsz, 256>>>(fc2_w, fc2_b, out);
}